// round 1
// baseline (speedup 1.0000x reference)
#include <cuda_runtime.h>
#include <cuda_bf16.h>
#include <math.h>

// GIN layer: out = h + relu(BN(relu(((1+eps)h + segsum(h[src]->dst)) @ W1 + b1) @ W2 + b2))
// N = 100000, D = 128, E = 1.6M. Output fp32 [N, D].

#define D 128
#define MAXN 100000

// Scratch (alloc-free rule: __device__ globals).
__device__ float g_buf1[MAXN * D];   // x_pre -> (later) y2
__device__ float g_buf2[MAXN * D];   // y1
__device__ float g_sum[D];
__device__ float g_sumsq[D];
__device__ float g_scale[D];
__device__ float g_shift[D];

// ---------------------------------------------------------------------------
// K1: x_pre = (1+eps)*h ; also zero the BN accumulators (block 0).
// ---------------------------------------------------------------------------
__global__ __launch_bounds__(256) void k_init(const float* __restrict__ h,
                                              const float* __restrict__ eps,
                                              int n_elem4) {
    if (blockIdx.x == 0 && threadIdx.x < D) {
        g_sum[threadIdx.x] = 0.f;
        g_sumsq[threadIdx.x] = 0.f;
    }
    const float s = 1.0f + eps[0];
    int i = blockIdx.x * blockDim.x + threadIdx.x;
    int stride = gridDim.x * blockDim.x;
    const float4* h4 = (const float4*)h;
    float4* o4 = (float4*)g_buf1;
    for (; i < n_elem4; i += stride) {
        float4 v = h4[i];
        v.x *= s; v.y *= s; v.z *= s; v.w *= s;
        o4[i] = v;
    }
}

// ---------------------------------------------------------------------------
// K2: edge scatter: g_buf1[dst] += h[src]. One warp per edge, float4 per lane.
// ---------------------------------------------------------------------------
__global__ __launch_bounds__(256) void k_scatter(const float* __restrict__ h,
                                                 const int* __restrict__ src,
                                                 const int* __restrict__ dst,
                                                 int E) {
    int e = blockIdx.x * (blockDim.x >> 5) + (threadIdx.x >> 5);
    if (e >= E) return;
    int lane = threadIdx.x & 31;
    int s = src[e];
    int d = dst[e];
    float4 v = ((const float4*)(h + (size_t)s * D))[lane];
    float* p = g_buf1 + (size_t)d * D + lane * 4;
    atomicAdd(p + 0, v.x);
    atomicAdd(p + 1, v.y);
    atomicAdd(p + 2, v.z);
    atomicAdd(p + 3, v.w);
}

// ---------------------------------------------------------------------------
// K3/K4: Y = act(A @ W + b). A:[N,128] W:[128,128] row-major (k,n). b:[128].
// Block tile 64(M) x 128(N), full K=128. 256 threads, 8x4 microtile each.
// smem: A tile 32KB + W chunk (32 rows) 16KB = 48KB static.
// ---------------------------------------------------------------------------
template <bool RELU>
__global__ __launch_bounds__(256) void k_gemm(const float* __restrict__ A,
                                              const float* __restrict__ W,
                                              const float* __restrict__ bias,
                                              float* __restrict__ Y,
                                              int N) {
    __shared__ float As[64 * D];   // 32 KB
    __shared__ float Ws[32 * D];   // 16 KB

    const int t = threadIdx.x;
    const int tx = t & 31;         // N dim: cols tx*4 .. tx*4+3
    const int ty = t >> 5;         // M dim: rows ty*8 .. ty*8+7
    const int rowBase = blockIdx.x * 64;

    // Load A tile (64x128): 2048 float4 slots; slot = i*256 + t (coalesced).
    #pragma unroll
    for (int i = 0; i < 8; i++) {
        int slot = i * 256 + t;
        int r = slot >> 5;          // 0..63
        int c4 = slot & 31;         // float4 column
        float4 v = make_float4(0.f, 0.f, 0.f, 0.f);
        if (rowBase + r < N)
            v = ((const float4*)(A + (size_t)(rowBase + r) * D))[c4];
        ((float4*)As)[slot] = v;
    }

    float acc[8][4];
    #pragma unroll
    for (int r = 0; r < 8; r++)
        #pragma unroll
        for (int j = 0; j < 4; j++) acc[r][j] = 0.f;

    for (int kc = 0; kc < 4; kc++) {
        __syncthreads();
        // Load W chunk rows [kc*32, kc*32+32): 1024 float4 slots.
        #pragma unroll
        for (int i = 0; i < 4; i++) {
            int slot = i * 256 + t;
            ((float4*)Ws)[slot] = ((const float4*)(W + (size_t)kc * 32 * D))[slot];
        }
        __syncthreads();

        #pragma unroll
        for (int k0 = 0; k0 < 32; k0 += 4) {
            float4 a4[8];
            #pragma unroll
            for (int r = 0; r < 8; r++)
                a4[r] = *(const float4*)&As[(ty * 8 + r) * D + kc * 32 + k0];
            #pragma unroll
            for (int kk = 0; kk < 4; kk++) {
                float4 b4 = *(const float4*)&Ws[(k0 + kk) * D + tx * 4];
                #pragma unroll
                for (int r = 0; r < 8; r++) {
                    float av = (kk == 0) ? a4[r].x : (kk == 1) ? a4[r].y
                             : (kk == 2) ? a4[r].z : a4[r].w;
                    acc[r][0] = fmaf(av, b4.x, acc[r][0]);
                    acc[r][1] = fmaf(av, b4.y, acc[r][1]);
                    acc[r][2] = fmaf(av, b4.z, acc[r][2]);
                    acc[r][3] = fmaf(av, b4.w, acc[r][3]);
                }
            }
        }
    }

    float4 b4 = ((const float4*)bias)[tx];
    #pragma unroll
    for (int r = 0; r < 8; r++) {
        int row = rowBase + ty * 8 + r;
        if (row >= N) break;
        float4 o;
        o.x = acc[r][0] + b4.x;
        o.y = acc[r][1] + b4.y;
        o.z = acc[r][2] + b4.z;
        o.w = acc[r][3] + b4.w;
        if (RELU) {
            o.x = fmaxf(o.x, 0.f); o.y = fmaxf(o.y, 0.f);
            o.z = fmaxf(o.z, 0.f); o.w = fmaxf(o.w, 0.f);
        }
        ((float4*)(Y + (size_t)row * D))[tx] = o;
    }
}

// ---------------------------------------------------------------------------
// K5: per-column sum / sumsq of Y (=g_buf1) into g_sum / g_sumsq.
// 256 threads: two row-lanes of 128 threads each, grid-strided.
// ---------------------------------------------------------------------------
__global__ __launch_bounds__(256) void k_colstats(const float* __restrict__ Y, int N) {
    __shared__ float ss[256], ss2[256];
    int c = threadIdx.x & (D - 1);
    int half = threadIdx.x >> 7;  // 0 or 1
    float s = 0.f, s2 = 0.f;
    for (int r = blockIdx.x * 2 + half; r < N; r += gridDim.x * 2) {
        float v = Y[(size_t)r * D + c];
        s += v;
        s2 = fmaf(v, v, s2);
    }
    ss[threadIdx.x] = s;
    ss2[threadIdx.x] = s2;
    __syncthreads();
    if (threadIdx.x < D) {
        s = ss[threadIdx.x] + ss[threadIdx.x + D];
        s2 = ss2[threadIdx.x] + ss2[threadIdx.x + D];
        atomicAdd(&g_sum[c], s);
        atomicAdd(&g_sumsq[c], s2);
    }
}

// ---------------------------------------------------------------------------
// K6: BN finalize -> scale/shift per column.
// ---------------------------------------------------------------------------
__global__ void k_bnfinal(const float* __restrict__ gamma,
                          const float* __restrict__ beta, float invN) {
    int c = threadIdx.x;
    float mean = g_sum[c] * invN;
    float var = g_sumsq[c] * invN - mean * mean;
    float rstd = rsqrtf(var + 1e-5f);
    float sc = rstd * gamma[c];
    g_scale[c] = sc;
    g_shift[c] = beta[c] - mean * sc;
}

// ---------------------------------------------------------------------------
// K7: out = h + relu(y2 * scale + shift)
// ---------------------------------------------------------------------------
__global__ __launch_bounds__(256) void k_epilogue(const float* __restrict__ h,
                                                  float* __restrict__ out,
                                                  int n_elem4) {
    int i = blockIdx.x * blockDim.x + threadIdx.x;
    int stride = gridDim.x * blockDim.x;
    const float4* y4 = (const float4*)g_buf1;
    const float4* h4 = (const float4*)h;
    float4* o4 = (float4*)out;
    for (; i < n_elem4; i += stride) {
        int c4 = (i & 31);  // float4 column index within row (D/4 = 32)
        float4 sc = ((const float4*)g_scale)[c4];
        float4 sh = ((const float4*)g_shift)[c4];
        float4 y = y4[i];
        float4 hv = h4[i];
        float4 o;
        o.x = hv.x + fmaxf(fmaf(y.x, sc.x, sh.x), 0.f);
        o.y = hv.y + fmaxf(fmaf(y.y, sc.y, sh.y), 0.f);
        o.z = hv.z + fmaxf(fmaf(y.z, sc.z, sh.z), 0.f);
        o.w = hv.w + fmaxf(fmaf(y.w, sc.w, sh.w), 0.f);
        o4[i] = o;
    }
}

// ---------------------------------------------------------------------------
// Inputs (metadata order): h, src, dst, eps, W1, b1, W2, b2, gamma, beta
// ---------------------------------------------------------------------------
extern "C" void kernel_launch(void* const* d_in, const int* in_sizes, int n_in,
                              void* d_out, int out_size) {
    const float* h     = (const float*)d_in[0];
    const int*   src   = (const int*)d_in[1];
    const int*   dst   = (const int*)d_in[2];
    const float* eps   = (const float*)d_in[3];
    const float* W1    = (const float*)d_in[4];
    const float* b1    = (const float*)d_in[5];
    const float* W2    = (const float*)d_in[6];
    const float* b2    = (const float*)d_in[7];
    const float* gamma = (const float*)d_in[8];
    const float* beta  = (const float*)d_in[9];
    float* out = (float*)d_out;

    const int N = in_sizes[0] / D;
    const int E = in_sizes[1];
    const int n_elem4 = N * D / 4;

    float* buf1;
    float* buf2;
    cudaGetSymbolAddress((void**)&buf1, g_buf1);
    cudaGetSymbolAddress((void**)&buf2, g_buf2);

    // K1: x_pre = (1+eps)*h, zero BN accumulators
    k_init<<<2048, 256>>>(h, eps, n_elem4);

    // K2: scatter-add neighbor messages
    int warpsPerBlock = 256 / 32;
    int nblk = (E + warpsPerBlock - 1) / warpsPerBlock;
    k_scatter<<<nblk, 256>>>(h, src, dst, E);

    // K3: y1 = relu(x_pre @ W1 + b1)
    int gblk = (N + 63) / 64;
    k_gemm<true><<<gblk, 256>>>(buf1, W1, b1, buf2, N);

    // K4: y2 = y1 @ W2 + b2  (overwrites buf1)
    k_gemm<false><<<gblk, 256>>>(buf2, W2, b2, buf1, N);

    // K5: column stats
    k_colstats<<<512, 256>>>(buf1, N);

    // K6: BN scale/shift
    k_bnfinal<<<1, D>>>(gamma, beta, 1.0f / (float)N);

    // K7: out = h + relu(y2*scale + shift)
    k_epilogue<<<2048, 256>>>(h, out, n_elem4);
}

// round 2
// speedup vs baseline: 1.6730x; 1.6730x over previous
#include <cuda_runtime.h>
#include <cuda_bf16.h>
#include <math.h>

// GIN layer: out = h + relu(BN(relu(((1+eps)h + segsum(h[src]->dst)) @ W1 + b1) @ W2 + b2))
// N = 100000, D = 128, E = 1.6M. Output fp32 [N, D].

#define D 128
#define MAXN 100000

// Scratch (alloc-free rule: __device__ globals). float4 for 16B-aligned red.v4.
__device__ float4 g_buf1_v4[MAXN * (D / 4)];   // x_pre -> (later) y2
__device__ float4 g_buf2_v4[MAXN * (D / 4)];   // y1
__device__ float g_sum[D];
__device__ float g_sumsq[D];
__device__ float g_scale[D];
__device__ float g_shift[D];

// ---------------------------------------------------------------------------
// K1: x_pre = (1+eps)*h ; also zero the BN accumulators (block 0).
// ---------------------------------------------------------------------------
__global__ __launch_bounds__(256) void k_init(const float* __restrict__ h,
                                              const float* __restrict__ eps,
                                              int n_elem4) {
    if (blockIdx.x == 0 && threadIdx.x < D) {
        g_sum[threadIdx.x] = 0.f;
        g_sumsq[threadIdx.x] = 0.f;
    }
    const float s = 1.0f + eps[0];
    int i = blockIdx.x * blockDim.x + threadIdx.x;
    int stride = gridDim.x * blockDim.x;
    const float4* h4 = (const float4*)h;
    for (; i < n_elem4; i += stride) {
        float4 v = h4[i];
        v.x *= s; v.y *= s; v.z *= s; v.w *= s;
        g_buf1_v4[i] = v;
    }
}

// ---------------------------------------------------------------------------
// K2: edge scatter: buf1[dst] += h[src]. One warp per edge, one red.v4 / lane.
// ---------------------------------------------------------------------------
__global__ __launch_bounds__(256) void k_scatter(const float* __restrict__ h,
                                                 const int* __restrict__ src,
                                                 const int* __restrict__ dst,
                                                 int E) {
    int e = blockIdx.x * (blockDim.x >> 5) + (threadIdx.x >> 5);
    if (e >= E) return;
    int lane = threadIdx.x & 31;
    int s = src[e];
    int d = dst[e];
    float4 v = ((const float4*)(h + (size_t)s * D))[lane];
    float4* p = g_buf1_v4 + (size_t)d * (D / 4) + lane;
    asm volatile(
        "red.global.add.v4.f32 [%0], {%1, %2, %3, %4};"
        :: "l"(p), "f"(v.x), "f"(v.y), "f"(v.z), "f"(v.w)
        : "memory");
}

// ---------------------------------------------------------------------------
// K3/K4: Y = act(A @ W + b). A:[N,128] W:[128,128] row-major (k,n). b:[128].
// Block tile 64(M) x 128(N), full K=128. 256 threads, 8x4 microtile each.
// STATS: when enabled (GEMM2), fuse per-column sum/sumsq accumulation.
// ---------------------------------------------------------------------------
template <bool RELU, bool STATS>
__global__ __launch_bounds__(256) void k_gemm(const float* __restrict__ A,
                                              const float* __restrict__ W,
                                              const float* __restrict__ bias,
                                              float* __restrict__ Y,
                                              int N) {
    __shared__ float As[64 * D];   // 32 KB
    __shared__ float Ws[32 * D];   // 16 KB
    __shared__ float csum[D], csumsq[D];

    const int t = threadIdx.x;
    const int tx = t & 31;         // N dim: cols tx*4 .. tx*4+3
    const int ty = t >> 5;         // M dim: rows ty*8 .. ty*8+7
    const int rowBase = blockIdx.x * 64;

    if (STATS && t < D) { csum[t] = 0.f; csumsq[t] = 0.f; }

    // Load A tile (64x128): 2048 float4 slots; slot = i*256 + t (coalesced).
    #pragma unroll
    for (int i = 0; i < 8; i++) {
        int slot = i * 256 + t;
        int r = slot >> 5;          // 0..63
        int c4 = slot & 31;         // float4 column
        float4 v = make_float4(0.f, 0.f, 0.f, 0.f);
        if (rowBase + r < N)
            v = ((const float4*)(A + (size_t)(rowBase + r) * D))[c4];
        ((float4*)As)[slot] = v;
    }

    float acc[8][4];
    #pragma unroll
    for (int r = 0; r < 8; r++)
        #pragma unroll
        for (int j = 0; j < 4; j++) acc[r][j] = 0.f;

    for (int kc = 0; kc < 4; kc++) {
        __syncthreads();
        // Load W chunk rows [kc*32, kc*32+32): 1024 float4 slots.
        #pragma unroll
        for (int i = 0; i < 4; i++) {
            int slot = i * 256 + t;
            ((float4*)Ws)[slot] = ((const float4*)(W + (size_t)kc * 32 * D))[slot];
        }
        __syncthreads();

        #pragma unroll
        for (int k0 = 0; k0 < 32; k0 += 4) {
            float4 a4[8];
            #pragma unroll
            for (int r = 0; r < 8; r++)
                a4[r] = *(const float4*)&As[(ty * 8 + r) * D + kc * 32 + k0];
            #pragma unroll
            for (int kk = 0; kk < 4; kk++) {
                float4 b4 = *(const float4*)&Ws[(k0 + kk) * D + tx * 4];
                #pragma unroll
                for (int r = 0; r < 8; r++) {
                    float av = (kk == 0) ? a4[r].x : (kk == 1) ? a4[r].y
                             : (kk == 2) ? a4[r].z : a4[r].w;
                    acc[r][0] = fmaf(av, b4.x, acc[r][0]);
                    acc[r][1] = fmaf(av, b4.y, acc[r][1]);
                    acc[r][2] = fmaf(av, b4.z, acc[r][2]);
                    acc[r][3] = fmaf(av, b4.w, acc[r][3]);
                }
            }
        }
    }

    float4 b4 = ((const float4*)bias)[tx];
    float lsum[4]  = {0.f, 0.f, 0.f, 0.f};
    float lsum2[4] = {0.f, 0.f, 0.f, 0.f};
    #pragma unroll
    for (int r = 0; r < 8; r++) {
        int row = rowBase + ty * 8 + r;
        if (row >= N) break;
        float4 o;
        o.x = acc[r][0] + b4.x;
        o.y = acc[r][1] + b4.y;
        o.z = acc[r][2] + b4.z;
        o.w = acc[r][3] + b4.w;
        if (RELU) {
            o.x = fmaxf(o.x, 0.f); o.y = fmaxf(o.y, 0.f);
            o.z = fmaxf(o.z, 0.f); o.w = fmaxf(o.w, 0.f);
        }
        if (STATS) {
            lsum[0] += o.x; lsum2[0] = fmaf(o.x, o.x, lsum2[0]);
            lsum[1] += o.y; lsum2[1] = fmaf(o.y, o.y, lsum2[1]);
            lsum[2] += o.z; lsum2[2] = fmaf(o.z, o.z, lsum2[2]);
            lsum[3] += o.w; lsum2[3] = fmaf(o.w, o.w, lsum2[3]);
        }
        ((float4*)(Y + (size_t)row * D))[tx] = o;
    }

    if (STATS) {
        __syncthreads();   // csum init visible; all accs done
        #pragma unroll
        for (int j = 0; j < 4; j++) {
            atomicAdd(&csum[tx * 4 + j], lsum[j]);
            atomicAdd(&csumsq[tx * 4 + j], lsum2[j]);
        }
        __syncthreads();
        if (t < D) {
            atomicAdd(&g_sum[t], csum[t]);
            atomicAdd(&g_sumsq[t], csumsq[t]);
        }
    }
}

// ---------------------------------------------------------------------------
// K5: BN finalize -> scale/shift per column.
// ---------------------------------------------------------------------------
__global__ void k_bnfinal(const float* __restrict__ gamma,
                          const float* __restrict__ beta, float invN) {
    int c = threadIdx.x;
    float mean = g_sum[c] * invN;
    float var = g_sumsq[c] * invN - mean * mean;
    float rstd = rsqrtf(var + 1e-5f);
    float sc = rstd * gamma[c];
    g_scale[c] = sc;
    g_shift[c] = beta[c] - mean * sc;
}

// ---------------------------------------------------------------------------
// K6: out = h + relu(y2 * scale + shift)
// ---------------------------------------------------------------------------
__global__ __launch_bounds__(256) void k_epilogue(const float* __restrict__ h,
                                                  float* __restrict__ out,
                                                  int n_elem4) {
    int i = blockIdx.x * blockDim.x + threadIdx.x;
    int stride = gridDim.x * blockDim.x;
    const float4* h4 = (const float4*)h;
    float4* o4 = (float4*)out;
    for (; i < n_elem4; i += stride) {
        int c4 = (i & 31);  // float4 column index within row (D/4 = 32)
        float4 sc = ((const float4*)g_scale)[c4];
        float4 sh = ((const float4*)g_shift)[c4];
        float4 y = g_buf1_v4[i];
        float4 hv = h4[i];
        float4 o;
        o.x = hv.x + fmaxf(fmaf(y.x, sc.x, sh.x), 0.f);
        o.y = hv.y + fmaxf(fmaf(y.y, sc.y, sh.y), 0.f);
        o.z = hv.z + fmaxf(fmaf(y.z, sc.z, sh.z), 0.f);
        o.w = hv.w + fmaxf(fmaf(y.w, sc.w, sh.w), 0.f);
        o4[i] = o;
    }
}

// ---------------------------------------------------------------------------
// Inputs (metadata order): h, src, dst, eps, W1, b1, W2, b2, gamma, beta
// ---------------------------------------------------------------------------
extern "C" void kernel_launch(void* const* d_in, const int* in_sizes, int n_in,
                              void* d_out, int out_size) {
    const float* h     = (const float*)d_in[0];
    const int*   src   = (const int*)d_in[1];
    const int*   dst   = (const int*)d_in[2];
    const float* eps   = (const float*)d_in[3];
    const float* W1    = (const float*)d_in[4];
    const float* b1    = (const float*)d_in[5];
    const float* W2    = (const float*)d_in[6];
    const float* b2    = (const float*)d_in[7];
    const float* gamma = (const float*)d_in[8];
    const float* beta  = (const float*)d_in[9];
    float* out = (float*)d_out;

    const int N = in_sizes[0] / D;
    const int E = in_sizes[1];
    const int n_elem4 = N * D / 4;

    float* buf1;
    float* buf2;
    cudaGetSymbolAddress((void**)&buf1, g_buf1_v4);
    cudaGetSymbolAddress((void**)&buf2, g_buf2_v4);

    // K1: x_pre = (1+eps)*h, zero BN accumulators
    k_init<<<2048, 256>>>(h, eps, n_elem4);

    // K2: scatter-add neighbor messages (red.global.add.v4.f32)
    int warpsPerBlock = 256 / 32;
    int nblk = (E + warpsPerBlock - 1) / warpsPerBlock;
    k_scatter<<<nblk, 256>>>(h, src, dst, E);

    // K3: y1 = relu(x_pre @ W1 + b1)
    int gblk = (N + 63) / 64;
    k_gemm<true, false><<<gblk, 256>>>(buf1, W1, b1, buf2, N);

    // K4: y2 = y1 @ W2 + b2, fused column stats (overwrites buf1)
    k_gemm<false, true><<<gblk, 256>>>(buf2, W2, b2, buf1, N);

    // K5: BN scale/shift
    k_bnfinal<<<1, D>>>(gamma, beta, 1.0f / (float)N);

    // K6: out = h + relu(y2*scale + shift)
    k_epilogue<<<2048, 256>>>(h, out, n_elem4);
}

// round 4
// speedup vs baseline: 1.7989x; 1.0752x over previous
#include <cuda_runtime.h>
#include <cuda_bf16.h>
#include <cstdint>
#include <math.h>

// GIN layer: out = h + relu(BN(relu(((1+eps)h + segsum(h[src]->dst)) @ W1 + b1) @ W2 + b2))
// Scatter via red.global.add.v4.f32; GEMMs via mma.sync bf16 split-precision (3 terms).
#define D 128
#define MAXN 100000

// ---- scratch (__device__ globals; alloc-free rule) ----
__device__ float4 g_buf1_v4[MAXN * (D / 4)];   // x_pre -> (later) y2
__device__ float4 g_buf2_v4[MAXN * (D / 4)];   // y1
// W^T fragments in exact mma B-register layout: [ks(8)][nt(16)][lane(32)] -> uint2
__device__ uint2 g_wf1_hi[4096], g_wf1_lo[4096];
__device__ uint2 g_wf2_hi[4096], g_wf2_lo[4096];
__device__ float g_sum[D], g_sumsq[D], g_scale[D], g_shift[D];

// ---------------------------------------------------------------------------
__device__ __forceinline__ void split2(float2 v, uint32_t& hi, uint32_t& lo) {
    __nv_bfloat162 h = __floats2bfloat162_rn(v.x, v.y);
    float2 hf = __bfloat1622float2(h);
    __nv_bfloat162 l = __floats2bfloat162_rn(v.x - hf.x, v.y - hf.y);
    hi = *(uint32_t*)&h;
    lo = *(uint32_t*)&l;
}

__device__ __forceinline__ void mma16816(float* c, const uint32_t* a, const uint2 b) {
    asm volatile(
        "mma.sync.aligned.m16n8k16.row.col.f32.bf16.bf16.f32 "
        "{%0,%1,%2,%3}, {%4,%5,%6,%7}, {%8,%9}, {%0,%1,%2,%3};"
        : "+f"(c[0]), "+f"(c[1]), "+f"(c[2]), "+f"(c[3])
        : "r"(a[0]), "r"(a[1]), "r"(a[2]), "r"(a[3]), "r"(b.x), "r"(b.y));
}

// ---------------------------------------------------------------------------
// K1: x_pre = (1+eps)*h ; zero BN accumulators.
// ---------------------------------------------------------------------------
__global__ __launch_bounds__(256) void k_init(const float* __restrict__ h,
                                              const float* __restrict__ eps,
                                              int n_elem4) {
    if (blockIdx.x == 0 && threadIdx.x < D) {
        g_sum[threadIdx.x] = 0.f;
        g_sumsq[threadIdx.x] = 0.f;
    }
    const float s = 1.0f + eps[0];
    int i = blockIdx.x * blockDim.x + threadIdx.x;
    int stride = gridDim.x * blockDim.x;
    const float4* h4 = (const float4*)h;
    for (; i < n_elem4; i += stride) {
        float4 v = h4[i];
        v.x *= s; v.y *= s; v.z *= s; v.w *= s;
        g_buf1_v4[i] = v;
    }
}

// ---------------------------------------------------------------------------
// K2: edge scatter via red.global.add.v4.f32 (one warp per edge).
// ---------------------------------------------------------------------------
__global__ __launch_bounds__(256) void k_scatter(const float* __restrict__ h,
                                                 const int* __restrict__ src,
                                                 const int* __restrict__ dst,
                                                 int E) {
    int e = blockIdx.x * (blockDim.x >> 5) + (threadIdx.x >> 5);
    if (e >= E) return;
    int lane = threadIdx.x & 31;
    int s = src[e];
    int d = dst[e];
    float4 v = ((const float4*)(h + (size_t)s * D))[lane];
    float4* p = g_buf1_v4 + (size_t)d * (D / 4) + lane;
    asm volatile("red.global.add.v4.f32 [%0], {%1, %2, %3, %4};"
                 :: "l"(p), "f"(v.x), "f"(v.y), "f"(v.z), "f"(v.w) : "memory");
}

// ---------------------------------------------------------------------------
// K-wprep: W [k=128][n=128] fp32 -> hi/lo bf16 fragments in mma B layout.
// item = ks*512 + nt*32 + lane. b0 = {W[k0][n], W[k0+1][n]}, b1 = k0+8 pair,
// with n = nt*8 + lane/4, k0 = ks*16 + (lane&3)*2. block 0 -> W1, 1 -> W2.
// ---------------------------------------------------------------------------
__global__ __launch_bounds__(256) void k_wprep(const float* __restrict__ W1,
                                               const float* __restrict__ W2) {
    const float* W = blockIdx.x == 0 ? W1 : W2;
    uint2* hi = blockIdx.x == 0 ? g_wf1_hi : g_wf2_hi;
    uint2* lo = blockIdx.x == 0 ? g_wf1_lo : g_wf2_lo;
    for (int item = threadIdx.x; item < 4096; item += 256) {
        int ks = item >> 9;
        int nt = (item >> 5) & 15;
        int lane = item & 31;
        int n = nt * 8 + (lane >> 2);
        int k0 = ks * 16 + (lane & 3) * 2;
        float2 vlo0 = make_float2(W[k0 * D + n], W[(k0 + 1) * D + n]);
        float2 vhi0 = make_float2(W[(k0 + 8) * D + n], W[(k0 + 9) * D + n]);
        uint2 h, l;
        split2(vlo0, h.x, l.x);
        split2(vhi0, h.y, l.y);
        hi[item] = h;
        lo[item] = l;
    }
}

// ---------------------------------------------------------------------------
// HMMA GEMM: Y = act(A @ W + b). Block = 128x128 output tile, 8 warps.
// Warp w: rows (w>>1)*32 .. +32 (2 m-tiles of 16), cols (w&1)*64 .. +64 (8 n-tiles).
// A fp32 read directly from gmem, split to bf16 hi/lo fragments on the fly.
// 3 mma terms: Ahi*Whi + Alo*Whi + Ahi*Wlo. STATS fuses BN column sums.
// ---------------------------------------------------------------------------
template <bool RELU, bool STATS>
__global__ __launch_bounds__(256) void k_gemm_mma(
    const float* __restrict__ A,
    const uint2* __restrict__ Whi, const uint2* __restrict__ Wlo,
    const float* __restrict__ bias,
    float* __restrict__ Y, int N) {
    __shared__ float csum[D], csumsq[D];
    const int t = threadIdx.x;
    const int w = t >> 5;
    const int lane = t & 31;
    const int blockRow = blockIdx.x * 128;

    if (STATS) {
        if (t < D) { csum[t] = 0.f; csumsq[t] = 0.f; }
        __syncthreads();
    }

    const int r0 = blockRow + (w >> 1) * 32 + (lane >> 2);  // mt=0 low row
    const int kq = (lane & 3) * 2;
    const int nhalf = (w & 1);

    // row validity (only last block can be partial)
    bool rv[2][2];
    #pragma unroll
    for (int mt = 0; mt < 2; mt++) {
        rv[mt][0] = (r0 + mt * 16) < N;
        rv[mt][1] = (r0 + mt * 16 + 8) < N;
    }

    float acc[2][8][4];
    #pragma unroll
    for (int mt = 0; mt < 2; mt++)
        #pragma unroll
        for (int nt = 0; nt < 8; nt++)
            #pragma unroll
            for (int j = 0; j < 4; j++) acc[mt][nt][j] = 0.f;

    #pragma unroll
    for (int ks = 0; ks < 8; ks++) {
        const int k0 = ks * 16 + kq;
        uint32_t ah[2][4], al[2][4];
        #pragma unroll
        for (int mt = 0; mt < 2; mt++) {
            const float* base = A + (size_t)(r0 + mt * 16) * D;
            float2 v0 = rv[mt][0] ? *(const float2*)(base + k0) : make_float2(0.f, 0.f);
            float2 v1 = rv[mt][1] ? *(const float2*)(base + 8 * D + k0) : make_float2(0.f, 0.f);
            float2 v2 = rv[mt][0] ? *(const float2*)(base + k0 + 8) : make_float2(0.f, 0.f);
            float2 v3 = rv[mt][1] ? *(const float2*)(base + 8 * D + k0 + 8) : make_float2(0.f, 0.f);
            split2(v0, ah[mt][0], al[mt][0]);
            split2(v1, ah[mt][1], al[mt][1]);
            split2(v2, ah[mt][2], al[mt][2]);
            split2(v3, ah[mt][3], al[mt][3]);
        }
        #pragma unroll
        for (int nt = 0; nt < 8; nt++) {
            int idx = (ks * 16 + nhalf * 8 + nt) * 32 + lane;
            uint2 bh = __ldg(&Whi[idx]);
            uint2 bl = __ldg(&Wlo[idx]);
            #pragma unroll
            for (int mt = 0; mt < 2; mt++) {
                mma16816(acc[mt][nt], ah[mt], bh);
                mma16816(acc[mt][nt], al[mt], bh);
                mma16816(acc[mt][nt], ah[mt], bl);
            }
        }
    }

    // epilogue
    #pragma unroll
    for (int nt = 0; nt < 8; nt++) {
        const int n0 = nhalf * 64 + nt * 8 + kq;
        float2 b2 = __ldg((const float2*)(bias + n0));
        float sA = 0.f, sB = 0.f, qA = 0.f, qB = 0.f;
        #pragma unroll
        for (int mt = 0; mt < 2; mt++) {
            float ox0 = acc[mt][nt][0] + b2.x;
            float oy0 = acc[mt][nt][1] + b2.y;
            float ox1 = acc[mt][nt][2] + b2.x;
            float oy1 = acc[mt][nt][3] + b2.y;
            if (RELU) {
                ox0 = fmaxf(ox0, 0.f); oy0 = fmaxf(oy0, 0.f);
                ox1 = fmaxf(ox1, 0.f); oy1 = fmaxf(oy1, 0.f);
            }
            int rlo = r0 + mt * 16;
            if (rv[mt][0]) {
                *(float2*)(Y + (size_t)rlo * D + n0) = make_float2(ox0, oy0);
                if (STATS) {
                    sA += ox0; qA = fmaf(ox0, ox0, qA);
                    sB += oy0; qB = fmaf(oy0, oy0, qB);
                }
            }
            if (rv[mt][1]) {
                *(float2*)(Y + (size_t)(rlo + 8) * D + n0) = make_float2(ox1, oy1);
                if (STATS) {
                    sA += ox1; qA = fmaf(ox1, ox1, qA);
                    sB += oy1; qB = fmaf(oy1, oy1, qB);
                }
            }
        }
        if (STATS) {
            // reduce across the 8 lanes sharing this column pair (stride 4)
            #pragma unroll
            for (int off = 4; off <= 16; off <<= 1) {
                sA += __shfl_xor_sync(0xFFFFFFFF, sA, off);
                sB += __shfl_xor_sync(0xFFFFFFFF, sB, off);
                qA += __shfl_xor_sync(0xFFFFFFFF, qA, off);
                qB += __shfl_xor_sync(0xFFFFFFFF, qB, off);
            }
            if (lane < 4) {
                atomicAdd(&csum[n0], sA);
                atomicAdd(&csum[n0 + 1], sB);
                atomicAdd(&csumsq[n0], qA);
                atomicAdd(&csumsq[n0 + 1], qB);
            }
        }
    }

    if (STATS) {
        __syncthreads();
        if (t < D) {
            atomicAdd(&g_sum[t], csum[t]);
            atomicAdd(&g_sumsq[t], csumsq[t]);
        }
    }
}

// ---------------------------------------------------------------------------
__global__ void k_bnfinal(const float* __restrict__ gamma,
                          const float* __restrict__ beta, float invN) {
    int c = threadIdx.x;
    float mean = g_sum[c] * invN;
    float var = g_sumsq[c] * invN - mean * mean;
    float rstd = rsqrtf(var + 1e-5f);
    float sc = rstd * gamma[c];
    g_scale[c] = sc;
    g_shift[c] = beta[c] - mean * sc;
}

__global__ __launch_bounds__(256) void k_epilogue(const float* __restrict__ h,
                                                  float* __restrict__ out,
                                                  int n_elem4) {
    int i = blockIdx.x * blockDim.x + threadIdx.x;
    int stride = gridDim.x * blockDim.x;
    const float4* h4 = (const float4*)h;
    float4* o4 = (float4*)out;
    for (; i < n_elem4; i += stride) {
        int c4 = (i & 31);
        float4 sc = ((const float4*)g_scale)[c4];
        float4 sh = ((const float4*)g_shift)[c4];
        float4 y = g_buf1_v4[i];  // y2 lives in buf1
        float4 hv = h4[i];
        float4 o;
        o.x = hv.x + fmaxf(fmaf(y.x, sc.x, sh.x), 0.f);
        o.y = hv.y + fmaxf(fmaf(y.y, sc.y, sh.y), 0.f);
        o.z = hv.z + fmaxf(fmaf(y.z, sc.z, sh.z), 0.f);
        o.w = hv.w + fmaxf(fmaf(y.w, sc.w, sh.w), 0.f);
        o4[i] = o;
    }
}

// ---------------------------------------------------------------------------
// Inputs: h, src, dst, eps, W1, b1, W2, b2, gamma, beta
// ---------------------------------------------------------------------------
extern "C" void kernel_launch(void* const* d_in, const int* in_sizes, int n_in,
                              void* d_out, int out_size) {
    const float* h     = (const float*)d_in[0];
    const int*   src   = (const int*)d_in[1];
    const int*   dst   = (const int*)d_in[2];
    const float* eps   = (const float*)d_in[3];
    const float* W1    = (const float*)d_in[4];
    const float* b1    = (const float*)d_in[5];
    const float* W2    = (const float*)d_in[6];
    const float* b2    = (const float*)d_in[7];
    const float* gamma = (const float*)d_in[8];
    const float* beta  = (const float*)d_in[9];
    float* out = (float*)d_out;

    const int N = in_sizes[0] / D;
    const int E = in_sizes[1];
    const int n_elem4 = N * D / 4;
    const int ntiles = (N + 127) / 128;

    float* buf1;  float* buf2;
    uint2 *wf1h, *wf1l, *wf2h, *wf2l;
    cudaGetSymbolAddress((void**)&buf1, g_buf1_v4);
    cudaGetSymbolAddress((void**)&buf2, g_buf2_v4);
    cudaGetSymbolAddress((void**)&wf1h, g_wf1_hi);
    cudaGetSymbolAddress((void**)&wf1l, g_wf1_lo);
    cudaGetSymbolAddress((void**)&wf2h, g_wf2_hi);
    cudaGetSymbolAddress((void**)&wf2l, g_wf2_lo);

    // K1: x_pre = (1+eps)*h (into buf1), zero BN accumulators
    k_init<<<2048, 256>>>(h, eps, n_elem4);
    // W fragment prep
    k_wprep<<<2, 256>>>(W1, W2);

    // K2: scatter-add neighbor messages
    int warpsPerBlock = 256 / 32;
    int nblk = (E + warpsPerBlock - 1) / warpsPerBlock;
    k_scatter<<<nblk, 256>>>(h, src, dst, E);

    // K3: y1 = relu(x_pre @ W1 + b1)  (buf1 -> buf2)
    k_gemm_mma<true, false><<<ntiles, 256>>>(buf1, wf1h, wf1l, b1, buf2, N);
    // K4: y2 = y1 @ W2 + b2, fused column stats (buf2 -> buf1)
    k_gemm_mma<false, true><<<ntiles, 256>>>(buf2, wf2h, wf2l, b2, buf1, N);

    // K5: BN scale/shift
    k_bnfinal<<<1, D>>>(gamma, beta, 1.0f / (float)N);
    // K6: out = h + relu(y2*scale + shift)
    k_epilogue<<<2048, 256>>>(h, out, n_elem4);
}

// round 5
// speedup vs baseline: 2.6099x; 1.4509x over previous
#include <cuda_runtime.h>
#include <cuda_bf16.h>
#include <cstdint>
#include <math.h>

// GIN layer: out = h + relu(BN(relu(((1+eps)h + segsum(h[src]->dst)) @ W1 + b1) @ W2 + b2))
// CSR-built gather-aggregate + split-bf16 mma.sync GEMMs (3 terms) + fused BN stats.
#define D 128
#define MAXN 100000
#define MAXE 1600000

// ---- scratch (__device__ globals; alloc-free rule) ----
__device__ float4 g_buf1_v4[MAXN * (D / 4)];   // x_pre -> (later) y2
__device__ float4 g_buf2_v4[MAXN * (D / 4)];   // y1
__device__ int g_cnt[MAXN];                    // degree histogram
__device__ int g_cur[MAXN];                    // placement cursors
__device__ int g_startp[MAXN];                 // exclusive scan (within 256-block)
__device__ int g_bsum[512];                    // per-block totals
__device__ int g_boff[512];                    // exclusive scan of block totals
__device__ int g_ssrc[MAXE];                   // src sorted by dst
// W fragments, mma B layout, interleaved: uint4{bhi.x,bhi.y,blo.x,blo.y}
// index = (ks*16 + nt)*32 + lane, ks=0..7, nt=0..15
__device__ uint4 g_wf1[4096], g_wf2[4096];
__device__ float g_sum[D], g_sumsq[D], g_scale[D], g_shift[D];

// ---------------------------------------------------------------------------
__device__ __forceinline__ void split2(float2 v, uint32_t& hi, uint32_t& lo) {
    __nv_bfloat162 h = __floats2bfloat162_rn(v.x, v.y);
    float2 hf = __bfloat1622float2(h);
    __nv_bfloat162 l = __floats2bfloat162_rn(v.x - hf.x, v.y - hf.y);
    hi = *(uint32_t*)&h;
    lo = *(uint32_t*)&l;
}

__device__ __forceinline__ void mma16816(float* c, const uint32_t* a,
                                         uint32_t b0, uint32_t b1) {
    asm volatile(
        "mma.sync.aligned.m16n8k16.row.col.f32.bf16.bf16.f32 "
        "{%0,%1,%2,%3}, {%4,%5,%6,%7}, {%8,%9}, {%0,%1,%2,%3};"
        : "+f"(c[0]), "+f"(c[1]), "+f"(c[2]), "+f"(c[3])
        : "r"(a[0]), "r"(a[1]), "r"(a[2]), "r"(a[3]), "r"(b0), "r"(b1));
}

// ---------------------------------------------------------------------------
// CSR build
// ---------------------------------------------------------------------------
__global__ __launch_bounds__(256) void k_zero(int N) {
    int i = blockIdx.x * 256 + threadIdx.x;
    if (i < N) { g_cnt[i] = 0; g_cur[i] = 0; }
    if (blockIdx.x == 0 && threadIdx.x < D) {
        g_sum[threadIdx.x] = 0.f;
        g_sumsq[threadIdx.x] = 0.f;
    }
}

__global__ __launch_bounds__(256) void k_hist(const int* __restrict__ dst, int E) {
    int e = blockIdx.x * 256 + threadIdx.x;
    if (e < E) atomicAdd(&g_cnt[dst[e]], 1);
}

__global__ __launch_bounds__(256) void k_scan1(int N) {
    int i = blockIdx.x * 256 + threadIdx.x;
    int lane = threadIdx.x & 31, wid = threadIdx.x >> 5;
    int v = (i < N) ? g_cnt[i] : 0;
    int x = v;
    #pragma unroll
    for (int o = 1; o < 32; o <<= 1) {
        int y = __shfl_up_sync(0xFFFFFFFF, x, o);
        if (lane >= o) x += y;
    }
    __shared__ int wt[8];
    if (lane == 31) wt[wid] = x;
    __syncthreads();
    if (wid == 0 && lane < 8) {
        int y = wt[lane];
        #pragma unroll
        for (int o = 1; o < 8; o <<= 1) {
            int z = __shfl_up_sync(0xFF, y, o);
            if (lane >= o) y += z;
        }
        wt[lane] = y;
    }
    __syncthreads();
    int incl = x + (wid > 0 ? wt[wid - 1] : 0);
    if (i < N) g_startp[i] = incl - v;
    if (threadIdx.x == 255) g_bsum[blockIdx.x] = incl;
}

__global__ __launch_bounds__(512) void k_scan2(int NB) {
    int t = threadIdx.x;
    int lane = t & 31, wid = t >> 5;
    int v = (t < NB) ? g_bsum[t] : 0;
    int x = v;
    #pragma unroll
    for (int o = 1; o < 32; o <<= 1) {
        int y = __shfl_up_sync(0xFFFFFFFF, x, o);
        if (lane >= o) x += y;
    }
    __shared__ int wt[16];
    if (lane == 31) wt[wid] = x;
    __syncthreads();
    if (wid == 0 && lane < 16) {
        int y = wt[lane];
        #pragma unroll
        for (int o = 1; o < 16; o <<= 1) {
            int z = __shfl_up_sync(0xFFFF, y, o);
            if (lane >= o) y += z;
        }
        wt[lane] = y;
    }
    __syncthreads();
    int incl = x + (wid > 0 ? wt[wid - 1] : 0);
    g_boff[t] = incl - v;
}

__global__ __launch_bounds__(256) void k_place(const int* __restrict__ src,
                                               const int* __restrict__ dst, int E) {
    int e = blockIdx.x * 256 + threadIdx.x;
    if (e >= E) return;
    int d = dst[e];
    int pos = g_startp[d] + g_boff[d >> 8] + atomicAdd(&g_cur[d], 1);
    g_ssrc[pos] = src[e];
}

// ---------------------------------------------------------------------------
// Aggregate: one warp per node. x_pre[n] = (1+eps)*h[n] + sum_j h[ssrc[j]].
// ---------------------------------------------------------------------------
__global__ __launch_bounds__(256) void k_aggregate(const float* __restrict__ h,
                                                   const float* __restrict__ eps,
                                                   int N) {
    int n = blockIdx.x * 8 + (threadIdx.x >> 5);
    if (n >= N) return;
    int lane = threadIdx.x & 31;
    const float4* h4 = (const float4*)h;
    float s = 1.0f + eps[0];
    float4 acc = h4[(size_t)n * 32 + lane];
    acc.x *= s; acc.y *= s; acc.z *= s; acc.w *= s;
    int start = g_startp[n] + g_boff[n >> 8];
    int deg = g_cnt[n];
    int j = 0;
    for (; j + 4 <= deg; j += 4) {
        int s0 = g_ssrc[start + j + 0];
        int s1 = g_ssrc[start + j + 1];
        int s2 = g_ssrc[start + j + 2];
        int s3 = g_ssrc[start + j + 3];
        float4 a0 = h4[(size_t)s0 * 32 + lane];
        float4 a1 = h4[(size_t)s1 * 32 + lane];
        float4 a2 = h4[(size_t)s2 * 32 + lane];
        float4 a3 = h4[(size_t)s3 * 32 + lane];
        acc.x += a0.x + a1.x + a2.x + a3.x;
        acc.y += a0.y + a1.y + a2.y + a3.y;
        acc.z += a0.z + a1.z + a2.z + a3.z;
        acc.w += a0.w + a1.w + a2.w + a3.w;
    }
    for (; j < deg; j++) {
        int s0 = g_ssrc[start + j];
        float4 a0 = h4[(size_t)s0 * 32 + lane];
        acc.x += a0.x; acc.y += a0.y; acc.z += a0.z; acc.w += a0.w;
    }
    g_buf1_v4[(size_t)n * 32 + lane] = acc;
}

// ---------------------------------------------------------------------------
// K-wprep: W [k=128][n=128] fp32 -> interleaved hi/lo bf16 fragments (B layout).
// item = (ks*16 + nt)*32 + lane; n = nt*8 + lane/4, k0 = ks*16 + (lane&3)*2.
// uint4 = {bhi(k0,k0+1), bhi(k0+8,k0+9), blo(k0,k0+1), blo(k0+8,k0+9)}
// stored as {h.x, h.y, l.x, l.y}. block 0 -> W1, 1 -> W2.
// ---------------------------------------------------------------------------
__global__ __launch_bounds__(256) void k_wprep(const float* __restrict__ W1,
                                               const float* __restrict__ W2) {
    const float* W = blockIdx.x == 0 ? W1 : W2;
    uint4* wf = blockIdx.x == 0 ? g_wf1 : g_wf2;
    for (int item = threadIdx.x; item < 4096; item += 256) {
        int ks = item >> 9;
        int nt = (item >> 5) & 15;
        int lane = item & 31;
        int n = nt * 8 + (lane >> 2);
        int k0 = ks * 16 + (lane & 3) * 2;
        float2 p0 = make_float2(W[k0 * D + n], W[(k0 + 1) * D + n]);
        float2 p1 = make_float2(W[(k0 + 8) * D + n], W[(k0 + 9) * D + n]);
        uint4 q;
        split2(p0, q.x, q.z);
        split2(p1, q.y, q.w);
        wf[item] = q;
    }
}

// ---------------------------------------------------------------------------
// HMMA GEMM: CTA = 64 rows x 128 cols, 8 warps; warp = 16 rows x 64 cols.
// acc[8][4] (32 regs). 3 split terms. STATS fuses BN column sums (GEMM2).
// ---------------------------------------------------------------------------
template <bool RELU, bool STATS>
__global__ __launch_bounds__(256) void k_gemm_mma(
    const float* __restrict__ A, const uint4* __restrict__ Wf,
    const float* __restrict__ bias, float* __restrict__ Y, int N) {
    __shared__ float csum[D], csumsq[D];
    const int t = threadIdx.x;
    const int w = t >> 5;
    const int lane = t & 31;

    if (STATS) {
        if (t < D) { csum[t] = 0.f; csumsq[t] = 0.f; }
        __syncthreads();
    }

    const int r0 = blockIdx.x * 64 + (w >> 1) * 16 + (lane >> 2);
    const int kq = (lane & 3) * 2;
    const int nhalf = w & 1;
    const bool rv0 = r0 < N;
    const bool rv1 = (r0 + 8) < N;

    float acc[8][4];
    #pragma unroll
    for (int nt = 0; nt < 8; nt++)
        #pragma unroll
        for (int j = 0; j < 4; j++) acc[nt][j] = 0.f;

    #pragma unroll
    for (int ks = 0; ks < 8; ks++) {
        const int k0 = ks * 16 + kq;
        const float* base = A + (size_t)r0 * D;
        float2 v0 = rv0 ? *(const float2*)(base + k0) : make_float2(0.f, 0.f);
        float2 v1 = rv1 ? *(const float2*)(base + 8 * D + k0) : make_float2(0.f, 0.f);
        float2 v2 = rv0 ? *(const float2*)(base + k0 + 8) : make_float2(0.f, 0.f);
        float2 v3 = rv1 ? *(const float2*)(base + 8 * D + k0 + 8) : make_float2(0.f, 0.f);
        uint32_t ah[4], al[4];
        split2(v0, ah[0], al[0]);
        split2(v1, ah[1], al[1]);
        split2(v2, ah[2], al[2]);
        split2(v3, ah[3], al[3]);
        #pragma unroll
        for (int nt = 0; nt < 8; nt++) {
            uint4 q = __ldg(&Wf[(ks * 16 + nhalf * 8 + nt) * 32 + lane]);
            mma16816(acc[nt], ah, q.x, q.y);   // Ahi * Whi
            mma16816(acc[nt], al, q.x, q.y);   // Alo * Whi
            mma16816(acc[nt], ah, q.z, q.w);   // Ahi * Wlo
        }
    }

    #pragma unroll
    for (int nt = 0; nt < 8; nt++) {
        const int n0 = nhalf * 64 + nt * 8 + kq;
        float2 b2 = __ldg((const float2*)(bias + n0));
        float ox0 = acc[nt][0] + b2.x;
        float oy0 = acc[nt][1] + b2.y;
        float ox1 = acc[nt][2] + b2.x;
        float oy1 = acc[nt][3] + b2.y;
        if (RELU) {
            ox0 = fmaxf(ox0, 0.f); oy0 = fmaxf(oy0, 0.f);
            ox1 = fmaxf(ox1, 0.f); oy1 = fmaxf(oy1, 0.f);
        }
        float sA = 0.f, sB = 0.f, qA = 0.f, qB = 0.f;
        if (rv0) {
            *(float2*)(Y + (size_t)r0 * D + n0) = make_float2(ox0, oy0);
            if (STATS) {
                sA += ox0; qA = fmaf(ox0, ox0, qA);
                sB += oy0; qB = fmaf(oy0, oy0, qB);
            }
        }
        if (rv1) {
            *(float2*)(Y + (size_t)(r0 + 8) * D + n0) = make_float2(ox1, oy1);
            if (STATS) {
                sA += ox1; qA = fmaf(ox1, ox1, qA);
                sB += oy1; qB = fmaf(oy1, oy1, qB);
            }
        }
        if (STATS) {
            #pragma unroll
            for (int off = 4; off <= 16; off <<= 1) {
                sA += __shfl_xor_sync(0xFFFFFFFF, sA, off);
                sB += __shfl_xor_sync(0xFFFFFFFF, sB, off);
                qA += __shfl_xor_sync(0xFFFFFFFF, qA, off);
                qB += __shfl_xor_sync(0xFFFFFFFF, qB, off);
            }
            if (lane < 4) {
                atomicAdd(&csum[n0], sA);
                atomicAdd(&csum[n0 + 1], sB);
                atomicAdd(&csumsq[n0], qA);
                atomicAdd(&csumsq[n0 + 1], qB);
            }
        }
    }

    if (STATS) {
        __syncthreads();
        if (t < D) {
            atomicAdd(&g_sum[t], csum[t]);
            atomicAdd(&g_sumsq[t], csumsq[t]);
        }
    }
}

// ---------------------------------------------------------------------------
__global__ void k_bnfinal(const float* __restrict__ gamma,
                          const float* __restrict__ beta, float invN) {
    int c = threadIdx.x;
    float mean = g_sum[c] * invN;
    float var = g_sumsq[c] * invN - mean * mean;
    float rstd = rsqrtf(var + 1e-5f);
    float sc = rstd * gamma[c];
    g_scale[c] = sc;
    g_shift[c] = beta[c] - mean * sc;
}

__global__ __launch_bounds__(256) void k_epilogue(const float* __restrict__ h,
                                                  float* __restrict__ out,
                                                  int n_elem4) {
    int i = blockIdx.x * blockDim.x + threadIdx.x;
    int stride = gridDim.x * blockDim.x;
    const float4* h4 = (const float4*)h;
    float4* o4 = (float4*)out;
    for (; i < n_elem4; i += stride) {
        int c4 = (i & 31);
        float4 sc = ((const float4*)g_scale)[c4];
        float4 sh = ((const float4*)g_shift)[c4];
        float4 y = g_buf1_v4[i];  // y2 lives in buf1
        float4 hv = h4[i];
        float4 o;
        o.x = hv.x + fmaxf(fmaf(y.x, sc.x, sh.x), 0.f);
        o.y = hv.y + fmaxf(fmaf(y.y, sc.y, sh.y), 0.f);
        o.z = hv.z + fmaxf(fmaf(y.z, sc.z, sh.z), 0.f);
        o.w = hv.w + fmaxf(fmaf(y.w, sc.w, sh.w), 0.f);
        o4[i] = o;
    }
}

// ---------------------------------------------------------------------------
// Inputs: h, src, dst, eps, W1, b1, W2, b2, gamma, beta
// ---------------------------------------------------------------------------
extern "C" void kernel_launch(void* const* d_in, const int* in_sizes, int n_in,
                              void* d_out, int out_size) {
    const float* h     = (const float*)d_in[0];
    const int*   src   = (const int*)d_in[1];
    const int*   dst   = (const int*)d_in[2];
    const float* eps   = (const float*)d_in[3];
    const float* W1    = (const float*)d_in[4];
    const float* b1    = (const float*)d_in[5];
    const float* W2    = (const float*)d_in[6];
    const float* b2    = (const float*)d_in[7];
    const float* gamma = (const float*)d_in[8];
    const float* beta  = (const float*)d_in[9];
    float* out = (float*)d_out;

    const int N = in_sizes[0] / D;
    const int E = in_sizes[1];
    const int n_elem4 = N * D / 4;
    const int NB = (N + 255) / 256;      // scan blocks (<=512)

    float* buf1;  float* buf2;
    uint4 *wf1, *wf2;
    cudaGetSymbolAddress((void**)&buf1, g_buf1_v4);
    cudaGetSymbolAddress((void**)&buf2, g_buf2_v4);
    cudaGetSymbolAddress((void**)&wf1, g_wf1);
    cudaGetSymbolAddress((void**)&wf2, g_wf2);

    // CSR build
    k_zero<<<NB, 256>>>(N);
    k_hist<<<(E + 255) / 256, 256>>>(dst, E);
    k_scan1<<<NB, 256>>>(N);
    k_scan2<<<1, 512>>>(NB);
    k_place<<<(E + 255) / 256, 256>>>(src, dst, E);
    // W fragment prep (overlappable)
    k_wprep<<<2, 256>>>(W1, W2);

    // Aggregate: x_pre -> buf1
    k_aggregate<<<(N + 7) / 8, 256>>>(h, eps, N);

    // GEMM1: y1 = relu(x_pre @ W1 + b1)  (buf1 -> buf2)
    const int gblk = (N + 63) / 64;
    k_gemm_mma<true, false><<<gblk, 256>>>(buf1, wf1, b1, buf2, N);
    // GEMM2: y2 = y1 @ W2 + b2, fused stats (buf2 -> buf1)
    k_gemm_mma<false, true><<<gblk, 256>>>(buf2, wf2, b2, buf1, N);

    k_bnfinal<<<1, D>>>(gamma, beta, 1.0f / (float)N);
    k_epilogue<<<2048, 256>>>(h, out, n_elem4);
}

// round 6
// speedup vs baseline: 2.7777x; 1.0643x over previous
#include <cuda_runtime.h>
#include <cuda_bf16.h>
#include <cstdint>
#include <math.h>

// GIN layer: out = h + relu(BN(relu(((1+eps)h + segsum(h[src]->dst)) @ W1 + b1) @ W2 + b2))
// CSR gather-aggregate + fused 2-GEMM MLP (split-bf16 mma.sync, y1 staged in smem).
#define D 128
#define MAXN 100000
#define MAXE 1600000

// ---- scratch (__device__ globals; alloc-free rule) ----
__device__ float4 g_buf1_v4[MAXN * (D / 4)];   // x_pre -> (in-place) y2
__device__ int g_cnt[MAXN];                    // degree histogram
__device__ int g_cur[MAXN];                    // placement cursors
__device__ int g_startp[MAXN];                 // exclusive scan (within 256-block)
__device__ int g_bsum[512];                    // per-block totals
__device__ int g_boff[512];                    // exclusive scan of block totals
__device__ int g_ssrc[MAXE];                   // src sorted by dst
// W fragments, mma B layout, interleaved: uint4{bhi.x,bhi.y,blo.x,blo.y}
__device__ uint4 g_wf1[4096], g_wf2[4096];
__device__ float g_sum[D], g_sumsq[D], g_scale[D], g_shift[D];

// ---------------------------------------------------------------------------
__device__ __forceinline__ void split2(float2 v, uint32_t& hi, uint32_t& lo) {
    __nv_bfloat162 h = __floats2bfloat162_rn(v.x, v.y);
    float2 hf = __bfloat1622float2(h);
    __nv_bfloat162 l = __floats2bfloat162_rn(v.x - hf.x, v.y - hf.y);
    hi = *(uint32_t*)&h;
    lo = *(uint32_t*)&l;
}

__device__ __forceinline__ void mma16816(float* c, const uint32_t* a,
                                         uint32_t b0, uint32_t b1) {
    asm volatile(
        "mma.sync.aligned.m16n8k16.row.col.f32.bf16.bf16.f32 "
        "{%0,%1,%2,%3}, {%4,%5,%6,%7}, {%8,%9}, {%0,%1,%2,%3};"
        : "+f"(c[0]), "+f"(c[1]), "+f"(c[2]), "+f"(c[3])
        : "r"(a[0]), "r"(a[1]), "r"(a[2]), "r"(a[3]), "r"(b0), "r"(b1));
}

// ---------------------------------------------------------------------------
// CSR build
// ---------------------------------------------------------------------------
__global__ __launch_bounds__(256) void k_zero(int N) {
    int i = blockIdx.x * 256 + threadIdx.x;
    if (i < N) { g_cnt[i] = 0; g_cur[i] = 0; }
    if (blockIdx.x == 0 && threadIdx.x < D) {
        g_sum[threadIdx.x] = 0.f;
        g_sumsq[threadIdx.x] = 0.f;
    }
}

__global__ __launch_bounds__(256) void k_hist(const int* __restrict__ dst, int E) {
    int e = blockIdx.x * 256 + threadIdx.x;
    if (e < E) atomicAdd(&g_cnt[dst[e]], 1);
}

__global__ __launch_bounds__(256) void k_scan1(int N) {
    int i = blockIdx.x * 256 + threadIdx.x;
    int lane = threadIdx.x & 31, wid = threadIdx.x >> 5;
    int v = (i < N) ? g_cnt[i] : 0;
    int x = v;
    #pragma unroll
    for (int o = 1; o < 32; o <<= 1) {
        int y = __shfl_up_sync(0xFFFFFFFF, x, o);
        if (lane >= o) x += y;
    }
    __shared__ int wt[8];
    if (lane == 31) wt[wid] = x;
    __syncthreads();
    if (wid == 0 && lane < 8) {
        int y = wt[lane];
        #pragma unroll
        for (int o = 1; o < 8; o <<= 1) {
            int z = __shfl_up_sync(0xFF, y, o);
            if (lane >= o) y += z;
        }
        wt[lane] = y;
    }
    __syncthreads();
    int incl = x + (wid > 0 ? wt[wid - 1] : 0);
    if (i < N) g_startp[i] = incl - v;
    if (threadIdx.x == 255) g_bsum[blockIdx.x] = incl;
}

__global__ __launch_bounds__(512) void k_scan2(int NB) {
    int t = threadIdx.x;
    int lane = t & 31, wid = t >> 5;
    int v = (t < NB) ? g_bsum[t] : 0;
    int x = v;
    #pragma unroll
    for (int o = 1; o < 32; o <<= 1) {
        int y = __shfl_up_sync(0xFFFFFFFF, x, o);
        if (lane >= o) x += y;
    }
    __shared__ int wt[16];
    if (lane == 31) wt[wid] = x;
    __syncthreads();
    if (wid == 0 && lane < 16) {
        int y = wt[lane];
        #pragma unroll
        for (int o = 1; o < 16; o <<= 1) {
            int z = __shfl_up_sync(0xFFFF, y, o);
            if (lane >= o) y += z;
        }
        wt[lane] = y;
    }
    __syncthreads();
    int incl = x + (wid > 0 ? wt[wid - 1] : 0);
    g_boff[t] = incl - v;
}

__global__ __launch_bounds__(256) void k_place(const int* __restrict__ src,
                                               const int* __restrict__ dst, int E) {
    int e = blockIdx.x * 256 + threadIdx.x;
    if (e >= E) return;
    int d = dst[e];
    int pos = g_startp[d] + g_boff[d >> 8] + atomicAdd(&g_cur[d], 1);
    g_ssrc[pos] = src[e];
}

// ---------------------------------------------------------------------------
// Aggregate: one warp per node. x_pre[n] = (1+eps)*h[n] + sum_j h[ssrc[j]].
// ---------------------------------------------------------------------------
__global__ __launch_bounds__(256) void k_aggregate(const float* __restrict__ h,
                                                   const float* __restrict__ eps,
                                                   int N) {
    int n = blockIdx.x * 8 + (threadIdx.x >> 5);
    if (n >= N) return;
    int lane = threadIdx.x & 31;
    const float4* h4 = (const float4*)h;
    float s = 1.0f + eps[0];
    float4 acc = h4[(size_t)n * 32 + lane];
    acc.x *= s; acc.y *= s; acc.z *= s; acc.w *= s;
    int start = g_startp[n] + g_boff[n >> 8];
    int deg = g_cnt[n];
    int j = 0;
    for (; j + 4 <= deg; j += 4) {
        int s0 = g_ssrc[start + j + 0];
        int s1 = g_ssrc[start + j + 1];
        int s2 = g_ssrc[start + j + 2];
        int s3 = g_ssrc[start + j + 3];
        float4 a0 = h4[(size_t)s0 * 32 + lane];
        float4 a1 = h4[(size_t)s1 * 32 + lane];
        float4 a2 = h4[(size_t)s2 * 32 + lane];
        float4 a3 = h4[(size_t)s3 * 32 + lane];
        acc.x += a0.x + a1.x + a2.x + a3.x;
        acc.y += a0.y + a1.y + a2.y + a3.y;
        acc.z += a0.z + a1.z + a2.z + a3.z;
        acc.w += a0.w + a1.w + a2.w + a3.w;
    }
    for (; j < deg; j++) {
        int s0 = g_ssrc[start + j];
        float4 a0 = h4[(size_t)s0 * 32 + lane];
        acc.x += a0.x; acc.y += a0.y; acc.z += a0.z; acc.w += a0.w;
    }
    g_buf1_v4[(size_t)n * 32 + lane] = acc;
}

// ---------------------------------------------------------------------------
// K-wprep: W [k=128][n=128] fp32 -> interleaved hi/lo bf16 fragments (B layout).
// ---------------------------------------------------------------------------
__global__ __launch_bounds__(256) void k_wprep(const float* __restrict__ W1,
                                               const float* __restrict__ W2) {
    const float* W = blockIdx.x == 0 ? W1 : W2;
    uint4* wf = blockIdx.x == 0 ? g_wf1 : g_wf2;
    for (int item = threadIdx.x; item < 4096; item += 256) {
        int ks = item >> 9;
        int nt = (item >> 5) & 15;
        int lane = item & 31;
        int n = nt * 8 + (lane >> 2);
        int k0 = ks * 16 + (lane & 3) * 2;
        float2 p0 = make_float2(W[k0 * D + n], W[(k0 + 1) * D + n]);
        float2 p1 = make_float2(W[(k0 + 8) * D + n], W[(k0 + 9) * D + n]);
        uint4 q;
        split2(p0, q.x, q.z);
        split2(p1, q.y, q.w);
        wf[item] = q;
    }
}

// ---------------------------------------------------------------------------
// Fused MLP: CTA = 64 rows. Stage 1: y1 = relu(x @ W1 + b1) -> smem bf16 hi/lo.
// Stage 2: y2 = y1 @ W2 + b2 -> gmem (in place over x), fused BN column stats.
// Warp tile 16x64 both stages; 8 warps.
// ---------------------------------------------------------------------------
#define Y1PITCH 132
__global__ __launch_bounds__(256) void k_mlp(
    const float* __restrict__ A,
    const uint4* __restrict__ W1f, const uint4* __restrict__ W2f,
    const float* __restrict__ b1, const float* __restrict__ b2,
    float* __restrict__ Y, int N) {
    __shared__ __nv_bfloat16 y1hi[64 * Y1PITCH];
    __shared__ __nv_bfloat16 y1lo[64 * Y1PITCH];
    __shared__ float csum[D], csumsq[D];

    const int t = threadIdx.x;
    const int w = t >> 5;
    const int lane = t & 31;

    if (t < D) { csum[t] = 0.f; csumsq[t] = 0.f; }

    const int rloc = (w >> 1) * 16 + (lane >> 2);   // local row (mt=0)
    const int r0 = blockIdx.x * 64 + rloc;          // global row
    const int kq = (lane & 3) * 2;
    const int nhalf = w & 1;
    const bool rv0 = r0 < N;
    const bool rv1 = (r0 + 8) < N;

    float acc[8][4];

    // ---------------- Stage 1: x @ W1 ----------------
    #pragma unroll
    for (int nt = 0; nt < 8; nt++)
        #pragma unroll
        for (int j = 0; j < 4; j++) acc[nt][j] = 0.f;

    #pragma unroll
    for (int ks = 0; ks < 8; ks++) {
        const int k0 = ks * 16 + kq;
        const float* base = A + (size_t)r0 * D;
        float2 v0 = rv0 ? *(const float2*)(base + k0) : make_float2(0.f, 0.f);
        float2 v1 = rv1 ? *(const float2*)(base + 8 * D + k0) : make_float2(0.f, 0.f);
        float2 v2 = rv0 ? *(const float2*)(base + k0 + 8) : make_float2(0.f, 0.f);
        float2 v3 = rv1 ? *(const float2*)(base + 8 * D + k0 + 8) : make_float2(0.f, 0.f);
        uint32_t ah[4], al[4];
        split2(v0, ah[0], al[0]);
        split2(v1, ah[1], al[1]);
        split2(v2, ah[2], al[2]);
        split2(v3, ah[3], al[3]);
        #pragma unroll
        for (int nt = 0; nt < 8; nt++) {
            uint4 q = __ldg(&W1f[(ks * 16 + nhalf * 8 + nt) * 32 + lane]);
            mma16816(acc[nt], ah, q.x, q.y);
            mma16816(acc[nt], al, q.x, q.y);
            mma16816(acc[nt], ah, q.z, q.w);
        }
    }

    // stage-1 epilogue: relu(acc+b1) -> smem hi/lo planes
    #pragma unroll
    for (int nt = 0; nt < 8; nt++) {
        const int n0 = nhalf * 64 + nt * 8 + kq;
        float2 b2v = __ldg((const float2*)(b1 + n0));
        float2 p0 = make_float2(fmaxf(acc[nt][0] + b2v.x, 0.f),
                                fmaxf(acc[nt][1] + b2v.y, 0.f));
        float2 p1 = make_float2(fmaxf(acc[nt][2] + b2v.x, 0.f),
                                fmaxf(acc[nt][3] + b2v.y, 0.f));
        uint32_t hi0, lo0, hi1, lo1;
        split2(p0, hi0, lo0);
        split2(p1, hi1, lo1);
        *(uint32_t*)&y1hi[rloc * Y1PITCH + n0] = hi0;
        *(uint32_t*)&y1lo[rloc * Y1PITCH + n0] = lo0;
        *(uint32_t*)&y1hi[(rloc + 8) * Y1PITCH + n0] = hi1;
        *(uint32_t*)&y1lo[(rloc + 8) * Y1PITCH + n0] = lo1;
    }
    __syncthreads();

    // ---------------- Stage 2: y1 @ W2 ----------------
    #pragma unroll
    for (int nt = 0; nt < 8; nt++)
        #pragma unroll
        for (int j = 0; j < 4; j++) acc[nt][j] = 0.f;

    #pragma unroll
    for (int ks = 0; ks < 8; ks++) {
        const int k0 = ks * 16 + kq;
        uint32_t ah[4], al[4];
        ah[0] = *(const uint32_t*)&y1hi[rloc * Y1PITCH + k0];
        ah[1] = *(const uint32_t*)&y1hi[(rloc + 8) * Y1PITCH + k0];
        ah[2] = *(const uint32_t*)&y1hi[rloc * Y1PITCH + k0 + 8];
        ah[3] = *(const uint32_t*)&y1hi[(rloc + 8) * Y1PITCH + k0 + 8];
        al[0] = *(const uint32_t*)&y1lo[rloc * Y1PITCH + k0];
        al[1] = *(const uint32_t*)&y1lo[(rloc + 8) * Y1PITCH + k0];
        al[2] = *(const uint32_t*)&y1lo[rloc * Y1PITCH + k0 + 8];
        al[3] = *(const uint32_t*)&y1lo[(rloc + 8) * Y1PITCH + k0 + 8];
        #pragma unroll
        for (int nt = 0; nt < 8; nt++) {
            uint4 q = __ldg(&W2f[(ks * 16 + nhalf * 8 + nt) * 32 + lane]);
            mma16816(acc[nt], ah, q.x, q.y);
            mma16816(acc[nt], al, q.x, q.y);
            mma16816(acc[nt], ah, q.z, q.w);
        }
    }

    // stage-2 epilogue: + b2, write y2, fused BN stats
    #pragma unroll
    for (int nt = 0; nt < 8; nt++) {
        const int n0 = nhalf * 64 + nt * 8 + kq;
        float2 b2v = __ldg((const float2*)(b2 + n0));
        float ox0 = acc[nt][0] + b2v.x;
        float oy0 = acc[nt][1] + b2v.y;
        float ox1 = acc[nt][2] + b2v.x;
        float oy1 = acc[nt][3] + b2v.y;
        float sA = 0.f, sB = 0.f, qA = 0.f, qB = 0.f;
        if (rv0) {
            *(float2*)(Y + (size_t)r0 * D + n0) = make_float2(ox0, oy0);
            sA += ox0; qA = fmaf(ox0, ox0, qA);
            sB += oy0; qB = fmaf(oy0, oy0, qB);
        }
        if (rv1) {
            *(float2*)(Y + (size_t)(r0 + 8) * D + n0) = make_float2(ox1, oy1);
            sA += ox1; qA = fmaf(ox1, ox1, qA);
            sB += oy1; qB = fmaf(oy1, oy1, qB);
        }
        #pragma unroll
        for (int off = 4; off <= 16; off <<= 1) {
            sA += __shfl_xor_sync(0xFFFFFFFF, sA, off);
            sB += __shfl_xor_sync(0xFFFFFFFF, sB, off);
            qA += __shfl_xor_sync(0xFFFFFFFF, qA, off);
            qB += __shfl_xor_sync(0xFFFFFFFF, qB, off);
        }
        if (lane < 4) {
            atomicAdd(&csum[n0], sA);
            atomicAdd(&csum[n0 + 1], sB);
            atomicAdd(&csumsq[n0], qA);
            atomicAdd(&csumsq[n0 + 1], qB);
        }
    }

    __syncthreads();
    if (t < D) {
        atomicAdd(&g_sum[t], csum[t]);
        atomicAdd(&g_sumsq[t], csumsq[t]);
    }
}

// ---------------------------------------------------------------------------
__global__ void k_bnfinal(const float* __restrict__ gamma,
                          const float* __restrict__ beta, float invN) {
    int c = threadIdx.x;
    float mean = g_sum[c] * invN;
    float var = g_sumsq[c] * invN - mean * mean;
    float rstd = rsqrtf(var + 1e-5f);
    float sc = rstd * gamma[c];
    g_scale[c] = sc;
    g_shift[c] = beta[c] - mean * sc;
}

__global__ __launch_bounds__(256) void k_epilogue(const float* __restrict__ h,
                                                  float* __restrict__ out,
                                                  int n_elem4) {
    int i = blockIdx.x * blockDim.x + threadIdx.x;
    int stride = gridDim.x * blockDim.x;
    const float4* h4 = (const float4*)h;
    float4* o4 = (float4*)out;
    for (; i < n_elem4; i += stride) {
        int c4 = (i & 31);
        float4 sc = ((const float4*)g_scale)[c4];
        float4 sh = ((const float4*)g_shift)[c4];
        float4 y = g_buf1_v4[i];  // y2 (in place)
        float4 hv = h4[i];
        float4 o;
        o.x = hv.x + fmaxf(fmaf(y.x, sc.x, sh.x), 0.f);
        o.y = hv.y + fmaxf(fmaf(y.y, sc.y, sh.y), 0.f);
        o.z = hv.z + fmaxf(fmaf(y.z, sc.z, sh.z), 0.f);
        o.w = hv.w + fmaxf(fmaf(y.w, sc.w, sh.w), 0.f);
        o4[i] = o;
    }
}

// ---------------------------------------------------------------------------
// Inputs: h, src, dst, eps, W1, b1, W2, b2, gamma, beta
// ---------------------------------------------------------------------------
extern "C" void kernel_launch(void* const* d_in, const int* in_sizes, int n_in,
                              void* d_out, int out_size) {
    const float* h     = (const float*)d_in[0];
    const int*   src   = (const int*)d_in[1];
    const int*   dst   = (const int*)d_in[2];
    const float* eps   = (const float*)d_in[3];
    const float* W1    = (const float*)d_in[4];
    const float* b1    = (const float*)d_in[5];
    const float* W2    = (const float*)d_in[6];
    const float* b2    = (const float*)d_in[7];
    const float* gamma = (const float*)d_in[8];
    const float* beta  = (const float*)d_in[9];
    float* out = (float*)d_out;

    const int N = in_sizes[0] / D;
    const int E = in_sizes[1];
    const int n_elem4 = N * D / 4;
    const int NB = (N + 255) / 256;

    float* buf1;
    uint4 *wf1, *wf2;
    cudaGetSymbolAddress((void**)&buf1, g_buf1_v4);
    cudaGetSymbolAddress((void**)&wf1, g_wf1);
    cudaGetSymbolAddress((void**)&wf2, g_wf2);

    // CSR build
    k_zero<<<NB, 256>>>(N);
    k_hist<<<(E + 255) / 256, 256>>>(dst, E);
    k_scan1<<<NB, 256>>>(N);
    k_scan2<<<1, 512>>>(NB);
    k_place<<<(E + 255) / 256, 256>>>(src, dst, E);
    // W fragment prep
    k_wprep<<<2, 256>>>(W1, W2);

    // Aggregate: x_pre -> buf1
    k_aggregate<<<(N + 7) / 8, 256>>>(h, eps, N);

    // Fused MLP: buf1 -> buf1 (y2), fused BN stats
    k_mlp<<<(N + 63) / 64, 256>>>(buf1, wf1, wf2, b1, b2, buf1, N);

    k_bnfinal<<<1, D>>>(gamma, beta, 1.0f / (float)N);
    k_epilogue<<<2048, 256>>>(h, out, n_elem4);
}

// round 7
// speedup vs baseline: 2.7976x; 1.0072x over previous
#include <cuda_runtime.h>
#include <cuda_bf16.h>
#include <cstdint>
#include <math.h>

// GIN layer: out = h + relu(BN(relu(((1+eps)h + segsum(h[src]->dst)) @ W1 + b1) @ W2 + b2))
// CSR build + single fused kernel: gather-aggregate -> GEMM1 -> GEMM2 (split-bf16 mma.sync).
#define D 128
#define MAXN 100000
#define MAXE 1600000

// ---- scratch (__device__ globals; alloc-free rule) ----
__device__ float4 g_buf1_v4[MAXN * (D / 4)];   // y2
__device__ int g_cnt[MAXN];                    // degree histogram
__device__ int g_cur[MAXN];                    // placement cursors
__device__ int g_startp[MAXN];                 // exclusive scan (within 256-block)
__device__ int g_bsum[512];                    // per-block totals
__device__ int g_boff[512];                    // exclusive scan of block totals
__device__ int g_ssrc[MAXE];                   // src sorted by dst
// W fragments, mma B layout, interleaved: uint4{bhi.x,bhi.y,blo.x,blo.y}
__device__ uint4 g_wf1[4096], g_wf2[4096];
__device__ float g_sum[D], g_sumsq[D], g_scale[D], g_shift[D];

// ---------------------------------------------------------------------------
__device__ __forceinline__ void split2(float2 v, uint32_t& hi, uint32_t& lo) {
    __nv_bfloat162 h = __floats2bfloat162_rn(v.x, v.y);
    float2 hf = __bfloat1622float2(h);
    __nv_bfloat162 l = __floats2bfloat162_rn(v.x - hf.x, v.y - hf.y);
    hi = *(uint32_t*)&h;
    lo = *(uint32_t*)&l;
}

__device__ __forceinline__ void mma16816(float* c, const uint32_t* a,
                                         uint32_t b0, uint32_t b1) {
    asm volatile(
        "mma.sync.aligned.m16n8k16.row.col.f32.bf16.bf16.f32 "
        "{%0,%1,%2,%3}, {%4,%5,%6,%7}, {%8,%9}, {%0,%1,%2,%3};"
        : "+f"(c[0]), "+f"(c[1]), "+f"(c[2]), "+f"(c[3])
        : "r"(a[0]), "r"(a[1]), "r"(a[2]), "r"(a[3]), "r"(b0), "r"(b1));
}

// ---------------------------------------------------------------------------
// CSR build
// ---------------------------------------------------------------------------
__global__ __launch_bounds__(256) void k_zero(int N) {
    int i = blockIdx.x * 256 + threadIdx.x;
    if (i < N) { g_cnt[i] = 0; g_cur[i] = 0; }
    if (blockIdx.x == 0 && threadIdx.x < D) {
        g_sum[threadIdx.x] = 0.f;
        g_sumsq[threadIdx.x] = 0.f;
    }
}

__global__ __launch_bounds__(256) void k_hist(const int* __restrict__ dst, int E) {
    int e = blockIdx.x * 256 + threadIdx.x;
    if (e < E) atomicAdd(&g_cnt[dst[e]], 1);
}

__global__ __launch_bounds__(256) void k_scan1(int N) {
    int i = blockIdx.x * 256 + threadIdx.x;
    int lane = threadIdx.x & 31, wid = threadIdx.x >> 5;
    int v = (i < N) ? g_cnt[i] : 0;
    int x = v;
    #pragma unroll
    for (int o = 1; o < 32; o <<= 1) {
        int y = __shfl_up_sync(0xFFFFFFFF, x, o);
        if (lane >= o) x += y;
    }
    __shared__ int wt[8];
    if (lane == 31) wt[wid] = x;
    __syncthreads();
    if (wid == 0 && lane < 8) {
        int y = wt[lane];
        #pragma unroll
        for (int o = 1; o < 8; o <<= 1) {
            int z = __shfl_up_sync(0xFF, y, o);
            if (lane >= o) y += z;
        }
        wt[lane] = y;
    }
    __syncthreads();
    int incl = x + (wid > 0 ? wt[wid - 1] : 0);
    if (i < N) g_startp[i] = incl - v;
    if (threadIdx.x == 255) g_bsum[blockIdx.x] = incl;
}

__global__ __launch_bounds__(512) void k_scan2(int NB) {
    int t = threadIdx.x;
    int lane = t & 31, wid = t >> 5;
    int v = (t < NB) ? g_bsum[t] : 0;
    int x = v;
    #pragma unroll
    for (int o = 1; o < 32; o <<= 1) {
        int y = __shfl_up_sync(0xFFFFFFFF, x, o);
        if (lane >= o) x += y;
    }
    __shared__ int wt[16];
    if (lane == 31) wt[wid] = x;
    __syncthreads();
    if (wid == 0 && lane < 16) {
        int y = wt[lane];
        #pragma unroll
        for (int o = 1; o < 16; o <<= 1) {
            int z = __shfl_up_sync(0xFFFF, y, o);
            if (lane >= o) y += z;
        }
        wt[lane] = y;
    }
    __syncthreads();
    int incl = x + (wid > 0 ? wt[wid - 1] : 0);
    g_boff[t] = incl - v;
}

__global__ __launch_bounds__(256) void k_place(const int* __restrict__ src,
                                               const int* __restrict__ dst, int E) {
    int e = blockIdx.x * 256 + threadIdx.x;
    if (e >= E) return;
    int d = dst[e];
    int pos = g_startp[d] + g_boff[d >> 8] + atomicAdd(&g_cur[d], 1);
    g_ssrc[pos] = src[e];
}

// ---------------------------------------------------------------------------
// K-wprep: W [k=128][n=128] fp32 -> interleaved hi/lo bf16 fragments (B layout).
// ---------------------------------------------------------------------------
__global__ __launch_bounds__(256) void k_wprep(const float* __restrict__ W1,
                                               const float* __restrict__ W2) {
    const float* W = blockIdx.x == 0 ? W1 : W2;
    uint4* wf = blockIdx.x == 0 ? g_wf1 : g_wf2;
    for (int item = threadIdx.x; item < 4096; item += 256) {
        int ks = item >> 9;
        int nt = (item >> 5) & 15;
        int lane = item & 31;
        int n = nt * 8 + (lane >> 2);
        int k0 = ks * 16 + (lane & 3) * 2;
        float2 p0 = make_float2(W[k0 * D + n], W[(k0 + 1) * D + n]);
        float2 p1 = make_float2(W[(k0 + 8) * D + n], W[(k0 + 9) * D + n]);
        uint4 q;
        split2(p0, q.x, q.z);
        split2(p1, q.y, q.w);
        wf[item] = q;
    }
}

// ---------------------------------------------------------------------------
// Fused: gather-aggregate + MLP. CTA = 64 nodes.
// Phase A: warp w gathers nodes w*8..w*8+7 -> split bf16 hi/lo smem planes.
// Phase B: stage-1 GEMM from planes, relu(+b1) overwrites planes.
// Phase C: stage-2 GEMM -> y2 gmem + fused BN column stats.
// Pitch 136 elems (68 words/row, 68 mod 32 = 4) -> conflict-free fragment LDS.
// ---------------------------------------------------------------------------
#define PITCH 136
__global__ __launch_bounds__(256) void k_fused(
    const float* __restrict__ h, const float* __restrict__ eps,
    const uint4* __restrict__ W1f, const uint4* __restrict__ W2f,
    const float* __restrict__ b1, const float* __restrict__ b2,
    float* __restrict__ Y, int N) {
    __shared__ __nv_bfloat16 plhi[64 * PITCH];
    __shared__ __nv_bfloat16 pllo[64 * PITCH];
    __shared__ float csum[D], csumsq[D];

    const int t = threadIdx.x;
    const int w = t >> 5;
    const int lane = t & 31;

    if (t < D) { csum[t] = 0.f; csumsq[t] = 0.f; }

    // ---------------- Phase A: gather ----------------
    {
        const float4* h4 = (const float4*)h;
        const float s = 1.0f + eps[0];
        #pragma unroll 1
        for (int i = 0; i < 8; i++) {
            int nl = w * 8 + i;
            int n = blockIdx.x * 64 + nl;
            float4 acc = make_float4(0.f, 0.f, 0.f, 0.f);
            if (n < N) {
                acc = h4[(size_t)n * 32 + lane];
                acc.x *= s; acc.y *= s; acc.z *= s; acc.w *= s;
                int start = g_startp[n] + g_boff[n >> 8];
                int deg = g_cnt[n];
                int j = 0;
                for (; j + 4 <= deg; j += 4) {
                    int s0 = g_ssrc[start + j + 0];
                    int s1 = g_ssrc[start + j + 1];
                    int s2 = g_ssrc[start + j + 2];
                    int s3 = g_ssrc[start + j + 3];
                    float4 a0 = h4[(size_t)s0 * 32 + lane];
                    float4 a1 = h4[(size_t)s1 * 32 + lane];
                    float4 a2 = h4[(size_t)s2 * 32 + lane];
                    float4 a3 = h4[(size_t)s3 * 32 + lane];
                    acc.x += a0.x + a1.x + a2.x + a3.x;
                    acc.y += a0.y + a1.y + a2.y + a3.y;
                    acc.z += a0.z + a1.z + a2.z + a3.z;
                    acc.w += a0.w + a1.w + a2.w + a3.w;
                }
                for (; j < deg; j++) {
                    int s0 = g_ssrc[start + j];
                    float4 a0 = h4[(size_t)s0 * 32 + lane];
                    acc.x += a0.x; acc.y += a0.y; acc.z += a0.z; acc.w += a0.w;
                }
            }
            uint32_t hi01, lo01, hi23, lo23;
            split2(make_float2(acc.x, acc.y), hi01, lo01);
            split2(make_float2(acc.z, acc.w), hi23, lo23);
            *(uint2*)&plhi[nl * PITCH + lane * 4] = make_uint2(hi01, hi23);
            *(uint2*)&pllo[nl * PITCH + lane * 4] = make_uint2(lo01, lo23);
        }
    }
    __syncthreads();

    const int rloc = (w >> 1) * 16 + (lane >> 2);
    const int r0 = blockIdx.x * 64 + rloc;
    const int kq = (lane & 3) * 2;
    const int nhalf = w & 1;
    const bool rv0 = r0 < N;
    const bool rv1 = (r0 + 8) < N;

    float acc[8][4];

    // ---------------- Phase B: stage-1 GEMM ----------------
    #pragma unroll
    for (int nt = 0; nt < 8; nt++)
        #pragma unroll
        for (int j = 0; j < 4; j++) acc[nt][j] = 0.f;

    #pragma unroll
    for (int ks = 0; ks < 8; ks++) {
        const int k0 = ks * 16 + kq;
        uint32_t ah[4], al[4];
        ah[0] = *(const uint32_t*)&plhi[rloc * PITCH + k0];
        ah[1] = *(const uint32_t*)&plhi[(rloc + 8) * PITCH + k0];
        ah[2] = *(const uint32_t*)&plhi[rloc * PITCH + k0 + 8];
        ah[3] = *(const uint32_t*)&plhi[(rloc + 8) * PITCH + k0 + 8];
        al[0] = *(const uint32_t*)&pllo[rloc * PITCH + k0];
        al[1] = *(const uint32_t*)&pllo[(rloc + 8) * PITCH + k0];
        al[2] = *(const uint32_t*)&pllo[rloc * PITCH + k0 + 8];
        al[3] = *(const uint32_t*)&pllo[(rloc + 8) * PITCH + k0 + 8];
        #pragma unroll
        for (int nt = 0; nt < 8; nt++) {
            uint4 q = __ldg(&W1f[(ks * 16 + nhalf * 8 + nt) * 32 + lane]);
            mma16816(acc[nt], ah, q.x, q.y);
            mma16816(acc[nt], al, q.x, q.y);
            mma16816(acc[nt], ah, q.z, q.w);
        }
    }
    __syncthreads();   // all reads of x planes done before overwrite

    // stage-1 epilogue: relu(acc+b1) -> planes (reuse)
    #pragma unroll
    for (int nt = 0; nt < 8; nt++) {
        const int n0 = nhalf * 64 + nt * 8 + kq;
        float2 bv = __ldg((const float2*)(b1 + n0));
        float2 p0 = make_float2(fmaxf(acc[nt][0] + bv.x, 0.f),
                                fmaxf(acc[nt][1] + bv.y, 0.f));
        float2 p1 = make_float2(fmaxf(acc[nt][2] + bv.x, 0.f),
                                fmaxf(acc[nt][3] + bv.y, 0.f));
        uint32_t hi0, lo0, hi1, lo1;
        split2(p0, hi0, lo0);
        split2(p1, hi1, lo1);
        *(uint32_t*)&plhi[rloc * PITCH + n0] = hi0;
        *(uint32_t*)&pllo[rloc * PITCH + n0] = lo0;
        *(uint32_t*)&plhi[(rloc + 8) * PITCH + n0] = hi1;
        *(uint32_t*)&pllo[(rloc + 8) * PITCH + n0] = lo1;
    }
    __syncthreads();

    // ---------------- Phase C: stage-2 GEMM ----------------
    #pragma unroll
    for (int nt = 0; nt < 8; nt++)
        #pragma unroll
        for (int j = 0; j < 4; j++) acc[nt][j] = 0.f;

    #pragma unroll
    for (int ks = 0; ks < 8; ks++) {
        const int k0 = ks * 16 + kq;
        uint32_t ah[4], al[4];
        ah[0] = *(const uint32_t*)&plhi[rloc * PITCH + k0];
        ah[1] = *(const uint32_t*)&plhi[(rloc + 8) * PITCH + k0];
        ah[2] = *(const uint32_t*)&plhi[rloc * PITCH + k0 + 8];
        ah[3] = *(const uint32_t*)&plhi[(rloc + 8) * PITCH + k0 + 8];
        al[0] = *(const uint32_t*)&pllo[rloc * PITCH + k0];
        al[1] = *(const uint32_t*)&pllo[(rloc + 8) * PITCH + k0];
        al[2] = *(const uint32_t*)&pllo[rloc * PITCH + k0 + 8];
        al[3] = *(const uint32_t*)&pllo[(rloc + 8) * PITCH + k0 + 8];
        #pragma unroll
        for (int nt = 0; nt < 8; nt++) {
            uint4 q = __ldg(&W2f[(ks * 16 + nhalf * 8 + nt) * 32 + lane]);
            mma16816(acc[nt], ah, q.x, q.y);
            mma16816(acc[nt], al, q.x, q.y);
            mma16816(acc[nt], ah, q.z, q.w);
        }
    }

    // stage-2 epilogue: + b2, write y2, fused BN stats
    #pragma unroll
    for (int nt = 0; nt < 8; nt++) {
        const int n0 = nhalf * 64 + nt * 8 + kq;
        float2 bv = __ldg((const float2*)(b2 + n0));
        float ox0 = acc[nt][0] + bv.x;
        float oy0 = acc[nt][1] + bv.y;
        float ox1 = acc[nt][2] + bv.x;
        float oy1 = acc[nt][3] + bv.y;
        float sA = 0.f, sB = 0.f, qA = 0.f, qB = 0.f;
        if (rv0) {
            *(float2*)(Y + (size_t)r0 * D + n0) = make_float2(ox0, oy0);
            sA += ox0; qA = fmaf(ox0, ox0, qA);
            sB += oy0; qB = fmaf(oy0, oy0, qB);
        }
        if (rv1) {
            *(float2*)(Y + (size_t)(r0 + 8) * D + n0) = make_float2(ox1, oy1);
            sA += ox1; qA = fmaf(ox1, ox1, qA);
            sB += oy1; qB = fmaf(oy1, oy1, qB);
        }
        #pragma unroll
        for (int off = 4; off <= 16; off <<= 1) {
            sA += __shfl_xor_sync(0xFFFFFFFF, sA, off);
            sB += __shfl_xor_sync(0xFFFFFFFF, sB, off);
            qA += __shfl_xor_sync(0xFFFFFFFF, qA, off);
            qB += __shfl_xor_sync(0xFFFFFFFF, qB, off);
        }
        if (lane < 4) {
            atomicAdd(&csum[n0], sA);
            atomicAdd(&csum[n0 + 1], sB);
            atomicAdd(&csumsq[n0], qA);
            atomicAdd(&csumsq[n0 + 1], qB);
        }
    }

    __syncthreads();
    if (t < D) {
        atomicAdd(&g_sum[t], csum[t]);
        atomicAdd(&g_sumsq[t], csumsq[t]);
    }
}

// ---------------------------------------------------------------------------
__global__ void k_bnfinal(const float* __restrict__ gamma,
                          const float* __restrict__ beta, float invN) {
    int c = threadIdx.x;
    float mean = g_sum[c] * invN;
    float var = g_sumsq[c] * invN - mean * mean;
    float rstd = rsqrtf(var + 1e-5f);
    float sc = rstd * gamma[c];
    g_scale[c] = sc;
    g_shift[c] = beta[c] - mean * sc;
}

__global__ __launch_bounds__(256) void k_epilogue(const float* __restrict__ h,
                                                  float* __restrict__ out,
                                                  int n_elem4) {
    int i = blockIdx.x * blockDim.x + threadIdx.x;
    int stride = gridDim.x * blockDim.x;
    const float4* h4 = (const float4*)h;
    float4* o4 = (float4*)out;
    for (; i < n_elem4; i += stride) {
        int c4 = (i & 31);
        float4 sc = ((const float4*)g_scale)[c4];
        float4 sh = ((const float4*)g_shift)[c4];
        float4 y = g_buf1_v4[i];
        float4 hv = h4[i];
        float4 o;
        o.x = hv.x + fmaxf(fmaf(y.x, sc.x, sh.x), 0.f);
        o.y = hv.y + fmaxf(fmaf(y.y, sc.y, sh.y), 0.f);
        o.z = hv.z + fmaxf(fmaf(y.z, sc.z, sh.z), 0.f);
        o.w = hv.w + fmaxf(fmaf(y.w, sc.w, sh.w), 0.f);
        o4[i] = o;
    }
}

// ---------------------------------------------------------------------------
// Inputs: h, src, dst, eps, W1, b1, W2, b2, gamma, beta
// ---------------------------------------------------------------------------
extern "C" void kernel_launch(void* const* d_in, const int* in_sizes, int n_in,
                              void* d_out, int out_size) {
    const float* h     = (const float*)d_in[0];
    const int*   src   = (const int*)d_in[1];
    const int*   dst   = (const int*)d_in[2];
    const float* eps   = (const float*)d_in[3];
    const float* W1    = (const float*)d_in[4];
    const float* b1    = (const float*)d_in[5];
    const float* W2    = (const float*)d_in[6];
    const float* b2    = (const float*)d_in[7];
    const float* gamma = (const float*)d_in[8];
    const float* beta  = (const float*)d_in[9];
    float* out = (float*)d_out;

    const int N = in_sizes[0] / D;
    const int E = in_sizes[1];
    const int n_elem4 = N * D / 4;
    const int NB = (N + 255) / 256;

    float* buf1;
    uint4 *wf1, *wf2;
    cudaGetSymbolAddress((void**)&buf1, g_buf1_v4);
    cudaGetSymbolAddress((void**)&wf1, g_wf1);
    cudaGetSymbolAddress((void**)&wf2, g_wf2);

    // CSR build
    k_zero<<<NB, 256>>>(N);
    k_hist<<<(E + 255) / 256, 256>>>(dst, E);
    k_scan1<<<NB, 256>>>(N);
    k_scan2<<<1, 512>>>(NB);
    k_place<<<(E + 255) / 256, 256>>>(src, dst, E);
    // W fragment prep
    k_wprep<<<2, 256>>>(W1, W2);

    // Fused gather + MLP: -> buf1 (y2), fused BN stats
    k_fused<<<(N + 63) / 64, 256>>>(h, eps, wf1, wf2, b1, b2, buf1, N);

    k_bnfinal<<<1, D>>>(gamma, beta, 1.0f / (float)N);
    k_epilogue<<<2048, 256>>>(h, out, n_elem4);
}